// round 1
// baseline (speedup 1.0000x reference)
#include <cuda_runtime.h>

#define NI 16384      // items
#define DD 64         // embedding dim
#define TT 8          // max tags
#define HH 256        // hidden
#define IPB 128       // items per block
#define NTHREADS 512

// smem layout (floats):
// [0,256)      item ids + lens
// [256,1280)   tag ids
// [2048,18432) Xs  : X^T [128 k][128 i]       (phase 1-2)
// [18432,26624) W1s: chunk [32][256]          (phase 2)
// [2048,34816) Hs  : H [128 i][256 k]         (phase 3, reuses Xs/W1s)
// [34816,51200) W2s: [256][64]                (phase 3)
#define SMEM_FLOATS 51200
#define SMEM_BYTES  (SMEM_FLOATS * 4)

__global__ __launch_bounds__(NTHREADS, 1)
void fused_tower(const int* __restrict__ item_ids,
                 const int* __restrict__ tag_ids,
                 const int* __restrict__ tag_lens,
                 const float* __restrict__ item_table,
                 const float* __restrict__ dat_table,
                 const float* __restrict__ tag_table,
                 const float* __restrict__ W1,
                 const float* __restrict__ b1,
                 const float* __restrict__ W2,
                 const float* __restrict__ b2,
                 float* __restrict__ out)
{
    extern __shared__ float smem[];
    int*   s_item = (int*)smem;          // [128]
    int*   s_len  = (int*)smem + 128;    // [128]
    int*   s_tag  = (int*)smem + 256;    // [1024]
    float* Xs  = smem + 2048;            // X^T: Xs[k*128 + i]
    float* W1s = smem + 18432;           // [32][256]
    float* Hs  = smem + 2048;            // [128][256] (reuse)
    float* W2s = smem + 34816;           // [256][64]

    const int tid = threadIdx.x;
    const int gi0 = blockIdx.x * IPB;

    // ---- load per-item metadata ----
    if (tid < IPB) {
        s_item[tid] = item_ids[gi0 + tid];
        s_len[tid]  = tag_lens[gi0 + tid];
    }
    for (int t = tid; t < IPB * TT; t += NTHREADS)
        s_tag[t] = tag_ids[gi0 * TT + t];
    __syncthreads();

    // ---- gather: e_item + ragged tag mean -> Xs (transposed, k-major) ----
    // slot = d4*128 + i  (i fast across lanes -> conflict-free STS)
    for (int s = tid; s < IPB * 16; s += NTHREADS) {
        const int i  = s & (IPB - 1);
        const int d4 = s >> 7;                 // 0..15 (float4 index)
        const long id = s_item[i];
        const float4 ei = __ldg((const float4*)(item_table + id * 64) + d4);
        const int len = s_len[i];
        float4 sum = make_float4(0.f, 0.f, 0.f, 0.f);
        for (int j = 0; j < len; j++) {
            const long tg = s_tag[i * TT + j];
            const float4 tv = __ldg((const float4*)(tag_table + tg * 64) + d4);
            sum.x += tv.x; sum.y += tv.y; sum.z += tv.z; sum.w += tv.w;
        }
        const float inv = 1.0f / (float)len;
        const int kb = d4 * 4;
        Xs[(kb + 0) * IPB + i] = ei.x;
        Xs[(kb + 1) * IPB + i] = ei.y;
        Xs[(kb + 2) * IPB + i] = ei.z;
        Xs[(kb + 3) * IPB + i] = ei.w;
        Xs[(64 + kb + 0) * IPB + i] = sum.x * inv;
        Xs[(64 + kb + 1) * IPB + i] = sum.y * inv;
        Xs[(64 + kb + 2) * IPB + i] = sum.z * inv;
        Xs[(64 + kb + 3) * IPB + i] = sum.w * inv;
    }

    // ---- e_dat gather -> output tail (coalesced) ----
    // slot = i*16 + d4 (d4 fast -> row-coalesced loads & stores)
    float* out_dat = out + (long)NI * DD;
    for (int s = tid; s < IPB * 16; s += NTHREADS) {
        const int d4 = s & 15;
        const int i  = s >> 4;
        const long id = s_item[i];
        const float4 v = __ldg((const float4*)(dat_table + id * 64) + d4);
        ((float4*)(out_dat + (long)(gi0 + i) * 64))[d4] = v;
    }
    __syncthreads();

    // ---- GEMM1: X[128,128] @ W1[0:128,256] -> H[128,256] (K=128: third
    //      chunk of tower input is zeros, so W1 rows 128..191 never matter) ----
    const int tx = tid & 31;   // 32 col-groups: cols tx*4..+3 and 128+tx*4..+3
    const int ty = tid >> 5;   // 16 row-groups: rows ty*8..+7
    float acc[8][8];
    #pragma unroll
    for (int r = 0; r < 8; r++)
        #pragma unroll
        for (int c = 0; c < 8; c++) acc[r][c] = 0.f;

    for (int k0 = 0; k0 < 128; k0 += 32) {
        // load W1 chunk [32][256] coalesced
        for (int t = tid; t < 2048; t += NTHREADS) {
            const int row = t >> 6, c4 = t & 63;
            ((float4*)W1s)[row * 64 + c4] =
                __ldg((const float4*)(W1 + (long)(k0 + row) * 256) + c4);
        }
        __syncthreads();
        #pragma unroll 8
        for (int kk = 0; kk < 32; kk++) {
            const float4 a0 = *(const float4*)(Xs + (k0 + kk) * IPB + ty * 8);
            const float4 a1 = *(const float4*)(Xs + (k0 + kk) * IPB + ty * 8 + 4);
            const float4 b0 = *(const float4*)(W1s + kk * 256 + tx * 4);
            const float4 b1v = *(const float4*)(W1s + kk * 256 + 128 + tx * 4);
            const float av[8] = {a0.x, a0.y, a0.z, a0.w, a1.x, a1.y, a1.z, a1.w};
            const float bv[8] = {b0.x, b0.y, b0.z, b0.w, b1v.x, b1v.y, b1v.z, b1v.w};
            #pragma unroll
            for (int r = 0; r < 8; r++)
                #pragma unroll
                for (int c = 0; c < 8; c++)
                    acc[r][c] = fmaf(av[r], bv[c], acc[r][c]);
        }
        __syncthreads();
    }

    // ---- bias + relu -> Hs ; load W2 -> W2s ----
    {
        const float4 bias0 = __ldg((const float4*)b1 + tx);
        const float4 bias1 = __ldg((const float4*)(b1 + 128) + tx);
        #pragma unroll
        for (int r = 0; r < 8; r++) {
            const int row = ty * 8 + r;
            float4 h0, h1;
            h0.x = fmaxf(acc[r][0] + bias0.x, 0.f);
            h0.y = fmaxf(acc[r][1] + bias0.y, 0.f);
            h0.z = fmaxf(acc[r][2] + bias0.z, 0.f);
            h0.w = fmaxf(acc[r][3] + bias0.w, 0.f);
            h1.x = fmaxf(acc[r][4] + bias1.x, 0.f);
            h1.y = fmaxf(acc[r][5] + bias1.y, 0.f);
            h1.z = fmaxf(acc[r][6] + bias1.z, 0.f);
            h1.w = fmaxf(acc[r][7] + bias1.w, 0.f);
            *(float4*)(Hs + row * 256 + tx * 4) = h0;
            *(float4*)(Hs + row * 256 + 128 + tx * 4) = h1;
        }
        for (int t = tid; t < 4096; t += NTHREADS)
            ((float4*)W2s)[t] = __ldg((const float4*)W2 + t);
    }
    __syncthreads();

    // ---- GEMM2: relu(H)[128,256] @ W2[256,64] + b2 -> out ----
    const int tx2 = tid & 15;  // cols tx2*4..+3
    const int ty2 = tid >> 4;  // rows ty2*4..+3
    float acc2[4][4];
    #pragma unroll
    for (int r = 0; r < 4; r++)
        #pragma unroll
        for (int c = 0; c < 4; c++) acc2[r][c] = 0.f;

    #pragma unroll 8
    for (int k = 0; k < 256; k++) {
        const float a0 = Hs[(ty2 * 4 + 0) * 256 + k];
        const float a1 = Hs[(ty2 * 4 + 1) * 256 + k];
        const float a2 = Hs[(ty2 * 4 + 2) * 256 + k];
        const float a3 = Hs[(ty2 * 4 + 3) * 256 + k];
        const float4 b = *(const float4*)(W2s + k * 64 + tx2 * 4);
        acc2[0][0] = fmaf(a0, b.x, acc2[0][0]);
        acc2[0][1] = fmaf(a0, b.y, acc2[0][1]);
        acc2[0][2] = fmaf(a0, b.z, acc2[0][2]);
        acc2[0][3] = fmaf(a0, b.w, acc2[0][3]);
        acc2[1][0] = fmaf(a1, b.x, acc2[1][0]);
        acc2[1][1] = fmaf(a1, b.y, acc2[1][1]);
        acc2[1][2] = fmaf(a1, b.z, acc2[1][2]);
        acc2[1][3] = fmaf(a1, b.w, acc2[1][3]);
        acc2[2][0] = fmaf(a2, b.x, acc2[2][0]);
        acc2[2][1] = fmaf(a2, b.y, acc2[2][1]);
        acc2[2][2] = fmaf(a2, b.z, acc2[2][2]);
        acc2[2][3] = fmaf(a2, b.w, acc2[2][3]);
        acc2[3][0] = fmaf(a3, b.x, acc2[3][0]);
        acc2[3][1] = fmaf(a3, b.y, acc2[3][1]);
        acc2[3][2] = fmaf(a3, b.z, acc2[3][2]);
        acc2[3][3] = fmaf(a3, b.w, acc2[3][3]);
    }

    {
        const float4 bias2 = __ldg((const float4*)b2 + tx2);
        #pragma unroll
        for (int r = 0; r < 4; r++) {
            float4 o;
            o.x = acc2[r][0] + bias2.x;
            o.y = acc2[r][1] + bias2.y;
            o.z = acc2[r][2] + bias2.z;
            o.w = acc2[r][3] + bias2.w;
            *(float4*)(out + (long)(gi0 + ty2 * 4 + r) * 64 + tx2 * 4) = o;
        }
    }
}

extern "C" void kernel_launch(void* const* d_in, const int* in_sizes, int n_in,
                              void* d_out, int out_size) {
    cudaFuncSetAttribute(fused_tower,
                         cudaFuncAttributeMaxDynamicSharedMemorySize, SMEM_BYTES);
    fused_tower<<<NI / IPB, NTHREADS, SMEM_BYTES>>>(
        (const int*)d_in[0],    // item_ids
        (const int*)d_in[1],    // tag_ids
        (const int*)d_in[2],    // tag_lens
        (const float*)d_in[3],  // item_table
        (const float*)d_in[4],  // item_dat_table
        (const float*)d_in[5],  // tag_table
        (const float*)d_in[6],  // W1
        (const float*)d_in[7],  // b1
        (const float*)d_in[8],  // W2
        (const float*)d_in[9],  // b2
        (float*)d_out);
}

// round 3
// speedup vs baseline: 2.0708x; 2.0708x over previous
#include <cuda_runtime.h>
#include <cuda_bf16.h>
#include <cstdint>

#define NI 16384
#define IPB 128
#define NTHREADS 512

// ---- smem regions (bytes) ----
// phase1: XH[128m][128k]bf16, XL, W1H[128k][256n]bf16, W1L
// phase3 (reuse): HH[128m][256k], HL, W2H[256k][64n], W2L
#define XH   0u
#define XL   32768u
#define W1H  65536u
#define W1L  131072u
#define HHO  0u
#define HLO  65536u
#define W2H  131072u
#define W2L  163840u
#define META 196608u
#define SMEM_BYTES 203008

static __device__ __forceinline__ uint32_t smem_u32(const void* p) {
    uint32_t a;
    asm("{ .reg .u64 t; cvta.to.shared.u64 t, %1; cvt.u32.u64 %0, t; }" : "=r"(a) : "l"(p));
    return a;
}
// swizzled byte offsets (conflict-free ldmatrix)
static __device__ __forceinline__ uint32_t xoff(int m, int k) {   // X: 256B rows
    return (uint32_t)(m * 256 + ((k * 2) ^ ((m & 7) * 16)));
}
static __device__ __forceinline__ uint32_t woff(int k, int n) {   // W1: 512B rows
    return (uint32_t)(k * 512 + ((n * 2) ^ ((k & 7) * 16)));
}
static __device__ __forceinline__ uint32_t hoff(int m, int k) {   // H: 512B rows
    return (uint32_t)(m * 512 + ((k * 2) ^ ((m & 7) * 16)));
}
static __device__ __forceinline__ uint32_t voff(int k, int n) {   // W2: 128B rows
    return (uint32_t)(k * 128 + ((n * 2) ^ ((k & 7) * 16)));
}
static __device__ __forceinline__ uint32_t b2u(__nv_bfloat162 v) {
    return *reinterpret_cast<uint32_t*>(&v);
}
static __device__ __forceinline__ void st_hilo2(char* sm, uint32_t offH, uint32_t offL,
                                                float a, float b) {
    __nv_bfloat162 h = __floats2bfloat162_rn(a, b);
    *(uint32_t*)(sm + offH) = b2u(h);
    __nv_bfloat162 l = __floats2bfloat162_rn(a - __bfloat162float(h.x),
                                             b - __bfloat162float(h.y));
    *(uint32_t*)(sm + offL) = b2u(l);
}
static __device__ __forceinline__ void st_hilo4(char* sm, uint32_t offH, uint32_t offL,
                                                float a, float b, float c, float d) {
    __nv_bfloat162 h0 = __floats2bfloat162_rn(a, b);
    __nv_bfloat162 h1 = __floats2bfloat162_rn(c, d);
    uint2 hv = make_uint2(b2u(h0), b2u(h1));
    *(uint2*)(sm + offH) = hv;
    __nv_bfloat162 l0 = __floats2bfloat162_rn(a - __bfloat162float(h0.x),
                                              b - __bfloat162float(h0.y));
    __nv_bfloat162 l1 = __floats2bfloat162_rn(c - __bfloat162float(h1.x),
                                              d - __bfloat162float(h1.y));
    uint2 lv = make_uint2(b2u(l0), b2u(l1));
    *(uint2*)(sm + offL) = lv;
}
static __device__ __forceinline__ void ldm_x4(uint32_t* r, uint32_t a) {
    asm volatile("ldmatrix.sync.aligned.m8n8.x4.shared.b16 {%0,%1,%2,%3}, [%4];"
        : "=r"(r[0]), "=r"(r[1]), "=r"(r[2]), "=r"(r[3]) : "r"(a));
}
static __device__ __forceinline__ void ldm_x4_t(uint32_t* r, uint32_t a) {
    asm volatile("ldmatrix.sync.aligned.m8n8.x4.trans.shared.b16 {%0,%1,%2,%3}, [%4];"
        : "=r"(r[0]), "=r"(r[1]), "=r"(r[2]), "=r"(r[3]) : "r"(a));
}
static __device__ __forceinline__ void mma16816(float* c, const uint32_t* a, const uint32_t* b) {
    asm volatile("mma.sync.aligned.m16n8k16.row.col.f32.bf16.bf16.f32 "
        "{%0,%1,%2,%3}, {%4,%5,%6,%7}, {%8,%9}, {%0,%1,%2,%3};"
        : "+f"(c[0]), "+f"(c[1]), "+f"(c[2]), "+f"(c[3])
        : "r"(a[0]), "r"(a[1]), "r"(a[2]), "r"(a[3]), "r"(b[0]), "r"(b[1]));
}

__global__ __launch_bounds__(NTHREADS, 1)
void fused_tower_mma(const int* __restrict__ item_ids,
                     const int* __restrict__ tag_ids,
                     const int* __restrict__ tag_lens,
                     const float* __restrict__ item_table,
                     const float* __restrict__ dat_table,
                     const float* __restrict__ tag_table,
                     const float* __restrict__ W1,
                     const float* __restrict__ b1,
                     const float* __restrict__ W2,
                     const float* __restrict__ b2,
                     float* __restrict__ out)
{
    extern __shared__ __align__(128) char sm[];
    const uint32_t smb = smem_u32(sm);
    const int tid = threadIdx.x;
    const int lane = tid & 31;
    const int wid = tid >> 5;
    const int gi0 = blockIdx.x * IPB;

    int*   s_item = (int*)(sm + META);
    int*   s_len  = (int*)(sm + META + 512);
    int*   s_tag  = (int*)(sm + META + 1024);
    float* b1s    = (float*)(sm + META + 5120);
    float* b2s    = (float*)(sm + META + 6144);

    // ---- metadata ----
    if (tid < IPB) {
        s_item[tid] = item_ids[gi0 + tid];
        s_len[tid]  = tag_lens[gi0 + tid];
    }
    for (int t = tid; t < IPB * 8; t += NTHREADS) s_tag[t] = tag_ids[gi0 * 8 + t];
    if (tid < 256) b1s[tid] = b1[tid];
    if (tid >= 256 && tid < 320) b2s[tid - 256] = b2[tid - 256];
    __syncthreads();

    // ---- gather: X rows (d4 fast => coalesced table reads, conflict-free STS) ----
    for (int s = tid; s < IPB * 16; s += NTHREADS) {
        const int d4 = s & 15;           // float4 index 0..15
        const int i  = s >> 4;
        const int id = s_item[i];
        const float4 ei = __ldg((const float4*)(item_table + (size_t)id * 64) + d4);
        const int len = s_len[i];
        float4 sum = make_float4(0.f, 0.f, 0.f, 0.f);
        for (int j = 0; j < len; j++) {
            const int tg = s_tag[i * 8 + j];
            const float4 tv = __ldg((const float4*)(tag_table + (size_t)tg * 64) + d4);
            sum.x += tv.x; sum.y += tv.y; sum.z += tv.z; sum.w += tv.w;
        }
        const float inv = 1.0f / (float)len;
        const uint32_t o0 = xoff(i, 4 * d4);
        st_hilo4(sm, XH + o0, XL + o0, ei.x, ei.y, ei.z, ei.w);
        const uint32_t o1 = xoff(i, 64 + 4 * d4);
        st_hilo4(sm, XH + o1, XL + o1, sum.x * inv, sum.y * inv, sum.z * inv, sum.w * inv);
    }
    // ---- W1 rows 0..127 -> smem bf16 hi/lo (coalesced, no transpose) ----
    for (int s = tid; s < 16384; s += NTHREADS) {
        const int k = s >> 7, n2 = s & 127;       // n = 2*n2
        const float2 v = __ldg((const float2*)(W1 + (size_t)k * 256) + n2);
        const uint32_t o = woff(k, 2 * n2);
        st_hilo2(sm, W1H + o, W1L + o, v.x, v.y);
    }
    // ---- e_dat -> out tail ----
    {
        float* out_dat = out + (size_t)NI * 64;
        for (int s = tid; s < IPB * 16; s += NTHREADS) {
            const int d4 = s & 15, i = s >> 4;
            const float4 v = __ldg((const float4*)(dat_table + (size_t)s_item[i] * 64) + d4);
            ((float4*)(out_dat + (size_t)(gi0 + i) * 64))[d4] = v;
        }
    }
    __syncthreads();

    // ---- GEMM1: C[128,256] = X @ W1, 3-pass bf16 split ----
    const int wm = wid >> 2, wn = wid & 3;        // 4x4 warp grid
    const int m0 = wm * 32, n0g = wn * 64;
    float acc[2][8][4];
    #pragma unroll
    for (int a = 0; a < 2; a++)
        #pragma unroll
        for (int j = 0; j < 8; j++)
            #pragma unroll
            for (int q = 0; q < 4; q++) acc[a][j][q] = 0.f;

    #pragma unroll
    for (int k0 = 0; k0 < 128; k0 += 16) {
        uint32_t Ah[2][4], Al[2][4];
        #pragma unroll
        for (int mt = 0; mt < 2; mt++) {
            const int r = m0 + mt * 16 + (lane & 15);
            const uint32_t o = xoff(r, k0 + ((lane >> 4) << 3));
            ldm_x4(Ah[mt], smb + XH + o);
            ldm_x4(Al[mt], smb + XL + o);
        }
        #pragma unroll
        for (int nh = 0; nh < 2; nh++) {
            uint32_t Bh[4][2], Bl[4][2];
            #pragma unroll
            for (int np = 0; np < 2; np++) {
                const int grp = lane >> 3;
                const int kr = k0 + (lane & 7) + ((grp & 1) << 3);
                const int nc = n0g + nh * 32 + np * 16 + ((grp >> 1) << 3);
                const uint32_t o = woff(kr, nc);
                uint32_t t[4];
                ldm_x4_t(t, smb + W1H + o);
                Bh[np * 2][0] = t[0]; Bh[np * 2][1] = t[1];
                Bh[np * 2 + 1][0] = t[2]; Bh[np * 2 + 1][1] = t[3];
                ldm_x4_t(t, smb + W1L + o);
                Bl[np * 2][0] = t[0]; Bl[np * 2][1] = t[1];
                Bl[np * 2 + 1][0] = t[2]; Bl[np * 2 + 1][1] = t[3];
            }
            #pragma unroll
            for (int mt = 0; mt < 2; mt++)
                #pragma unroll
                for (int nt = 0; nt < 4; nt++) {
                    float* c = acc[mt][nh * 4 + nt];
                    mma16816(c, Ah[mt], Bh[nt]);
                    mma16816(c, Ah[mt], Bl[nt]);
                    mma16816(c, Al[mt], Bh[nt]);
                }
        }
    }
    __syncthreads();   // all warps done reading X/W1 before overwrite

    // ---- stage W2 bf16 hi/lo ----
    for (int s = tid; s < 8192; s += NTHREADS) {
        const int k = s >> 5, n2 = s & 31;        // n = 2*n2
        const float2 v = __ldg((const float2*)(W2 + (size_t)k * 64) + n2);
        const uint32_t o = voff(k, 2 * n2);
        st_hilo2(sm, W2H + o, W2L + o, v.x, v.y);
    }
    // ---- H = relu(C + b1) -> smem hi/lo ----
    #pragma unroll
    for (int mt = 0; mt < 2; mt++)
        #pragma unroll
        for (int j = 0; j < 8; j++) {
            const int ncol = n0g + (j >> 2) * 32 + (j & 3) * 8 + 2 * (lane & 3);
            const float2 bias = *(const float2*)(b1s + ncol);
            const float* c = acc[mt][j];
            const int r = m0 + mt * 16 + (lane >> 2);
            const float f0 = fmaxf(c[0] + bias.x, 0.f);
            const float f1 = fmaxf(c[1] + bias.y, 0.f);
            const uint32_t o0 = hoff(r, ncol);
            st_hilo2(sm, HHO + o0, HLO + o0, f0, f1);
            const float f2 = fmaxf(c[2] + bias.x, 0.f);
            const float f3 = fmaxf(c[3] + bias.y, 0.f);
            const uint32_t o1 = hoff(r + 8, ncol);
            st_hilo2(sm, HHO + o1, HLO + o1, f2, f3);
        }
    __syncthreads();

    // ---- GEMM2: O[128,64] = H @ W2, 3-pass bf16 split ----
    const int m0b = (wid >> 1) * 16;              // 8x2 warp grid
    const int n0b = (wid & 1) * 32;
    float acc2[4][4];
    #pragma unroll
    for (int j = 0; j < 4; j++)
        #pragma unroll
        for (int q = 0; q < 4; q++) acc2[j][q] = 0.f;

    #pragma unroll
    for (int k0 = 0; k0 < 256; k0 += 16) {
        uint32_t Ah[4], Al[4];
        {
            const int r = m0b + (lane & 15);
            const uint32_t o = hoff(r, k0 + ((lane >> 4) << 3));
            ldm_x4(Ah, smb + HHO + o);
            ldm_x4(Al, smb + HLO + o);
        }
        uint32_t Bh[4][2], Bl[4][2];
        #pragma unroll
        for (int np = 0; np < 2; np++) {
            const int grp = lane >> 3;
            const int kr = k0 + (lane & 7) + ((grp & 1) << 3);
            const int nc = n0b + np * 16 + ((grp >> 1) << 3);
            const uint32_t o = voff(kr, nc);
            uint32_t t[4];
            ldm_x4_t(t, smb + W2H + o);
            Bh[np * 2][0] = t[0]; Bh[np * 2][1] = t[1];
            Bh[np * 2 + 1][0] = t[2]; Bh[np * 2 + 1][1] = t[3];
            ldm_x4_t(t, smb + W2L + o);
            Bl[np * 2][0] = t[0]; Bl[np * 2][1] = t[1];
            Bl[np * 2 + 1][0] = t[2]; Bl[np * 2 + 1][1] = t[3];
        }
        #pragma unroll
        for (int nt = 0; nt < 4; nt++) {
            mma16816(acc2[nt], Ah, Bh[nt]);
            mma16816(acc2[nt], Ah, Bl[nt]);
            mma16816(acc2[nt], Al, Bh[nt]);
        }
    }

    // ---- epilogue: out = O + b2 ----
    #pragma unroll
    for (int nt = 0; nt < 4; nt++) {
        const int n = n0b + nt * 8 + 2 * (lane & 3);
        const float2 bias = *(const float2*)(b2s + n);
        const int r = gi0 + m0b + (lane >> 2);
        float2 o0 = make_float2(acc2[nt][0] + bias.x, acc2[nt][1] + bias.y);
        float2 o1 = make_float2(acc2[nt][2] + bias.x, acc2[nt][3] + bias.y);
        *(float2*)(out + (size_t)r * 64 + n) = o0;
        *(float2*)(out + (size_t)(r + 8) * 64 + n) = o1;
    }
}

extern "C" void kernel_launch(void* const* d_in, const int* in_sizes, int n_in,
                              void* d_out, int out_size) {
    cudaFuncSetAttribute(fused_tower_mma,
                         cudaFuncAttributeMaxDynamicSharedMemorySize, SMEM_BYTES);
    fused_tower_mma<<<NI / IPB, NTHREADS, SMEM_BYTES>>>(
        (const int*)d_in[0], (const int*)d_in[1], (const int*)d_in[2],
        (const float*)d_in[3], (const float*)d_in[4], (const float*)d_in[5],
        (const float*)d_in[6], (const float*)d_in[7],
        (const float*)d_in[8], (const float*)d_in[9],
        (float*)d_out);
}

// round 4
// speedup vs baseline: 2.4127x; 1.1651x over previous
#include <cuda_runtime.h>
#include <cuda_fp16.h>
#include <cstdint>

#define NI 16384
#define IPB 64
#define NTHREADS 256
#define NBLK (NI / IPB)

// ---- smem byte regions ----
// phase1: XH[64m][128k]f16 16KB, XL 16KB, W1S[128k][256n]f16 64KB
// phase3 (reuse): HH[64m][256k] 32KB, HL 32KB, W2S[256k][64n] 32KB
#define XHO  0u
#define XLO  16384u
#define W1O  32768u
#define HHO  0u
#define HLO  32768u
#define W2O  65536u
#define META 98304u
#define SMEM_BYTES 103424

static __device__ __forceinline__ uint32_t smem_u32(const void* p) {
    uint32_t a;
    asm("{ .reg .u64 t; cvta.to.shared.u64 t, %1; cvt.u32.u64 %0, t; }" : "=r"(a) : "l"(p));
    return a;
}
// swizzled byte offsets (conflict-free ldmatrix)
static __device__ __forceinline__ uint32_t xoff(int m, int k) {   // 256B rows
    return (uint32_t)(m * 256 + ((k * 2) ^ ((m & 7) * 16)));
}
static __device__ __forceinline__ uint32_t woff(int k, int n) {   // 512B rows
    return (uint32_t)(k * 512 + ((n * 2) ^ ((k & 7) * 16)));
}
static __device__ __forceinline__ uint32_t hoff(int m, int k) {   // 512B rows
    return (uint32_t)(m * 512 + ((k * 2) ^ ((m & 7) * 16)));
}
static __device__ __forceinline__ uint32_t voff(int k, int n) {   // 128B rows
    return (uint32_t)(k * 128 + ((n * 2) ^ ((k & 7) * 16)));
}
static __device__ __forceinline__ uint32_t h2u(__half2 v) {
    return *reinterpret_cast<uint32_t*>(&v);
}
// A-operand: hi + lo fp16 split
static __device__ __forceinline__ void st_hilo2h(char* sm, uint32_t oH, uint32_t oL,
                                                 float a, float b) {
    __half2 h = __floats2half2_rn(a, b);
    *(uint32_t*)(sm + oH) = h2u(h);
    __half2 l = __floats2half2_rn(a - __low2float(h), b - __high2float(h));
    *(uint32_t*)(sm + oL) = h2u(l);
}
static __device__ __forceinline__ void st_hilo4h(char* sm, uint32_t oH, uint32_t oL,
                                                 float a, float b, float c, float d) {
    __half2 h0 = __floats2half2_rn(a, b), h1 = __floats2half2_rn(c, d);
    *(uint2*)(sm + oH) = make_uint2(h2u(h0), h2u(h1));
    __half2 l0 = __floats2half2_rn(a - __low2float(h0), b - __high2float(h0));
    __half2 l1 = __floats2half2_rn(c - __low2float(h1), d - __high2float(h1));
    *(uint2*)(sm + oL) = make_uint2(h2u(l0), h2u(l1));
}
// B-operand: single fp16
static __device__ __forceinline__ void st_h4(char* sm, uint32_t o, float4 v) {
    *(uint2*)(sm + o) = make_uint2(h2u(__floats2half2_rn(v.x, v.y)),
                                   h2u(__floats2half2_rn(v.z, v.w)));
}
static __device__ __forceinline__ void ldm_x4(uint32_t* r, uint32_t a) {
    asm volatile("ldmatrix.sync.aligned.m8n8.x4.shared.b16 {%0,%1,%2,%3}, [%4];"
        : "=r"(r[0]), "=r"(r[1]), "=r"(r[2]), "=r"(r[3]) : "r"(a));
}
static __device__ __forceinline__ void ldm_x4_t(uint32_t* r, uint32_t a) {
    asm volatile("ldmatrix.sync.aligned.m8n8.x4.trans.shared.b16 {%0,%1,%2,%3}, [%4];"
        : "=r"(r[0]), "=r"(r[1]), "=r"(r[2]), "=r"(r[3]) : "r"(a));
}
static __device__ __forceinline__ void mma16816h(float* c, const uint32_t* a, const uint32_t* b) {
    asm volatile("mma.sync.aligned.m16n8k16.row.col.f32.f16.f16.f32 "
        "{%0,%1,%2,%3}, {%4,%5,%6,%7}, {%8,%9}, {%0,%1,%2,%3};"
        : "+f"(c[0]), "+f"(c[1]), "+f"(c[2]), "+f"(c[3])
        : "r"(a[0]), "r"(a[1]), "r"(a[2]), "r"(a[3]), "r"(b[0]), "r"(b[1]));
}

__global__ __launch_bounds__(NTHREADS, 2)
void fused_tower_mma2(const int* __restrict__ item_ids,
                      const int* __restrict__ tag_ids,
                      const int* __restrict__ tag_lens,
                      const float* __restrict__ item_table,
                      const float* __restrict__ dat_table,
                      const float* __restrict__ tag_table,
                      const float* __restrict__ W1,
                      const float* __restrict__ b1,
                      const float* __restrict__ W2,
                      const float* __restrict__ b2,
                      float* __restrict__ out)
{
    extern __shared__ __align__(128) char sm[];
    const uint32_t smb = smem_u32(sm);
    const int tid = threadIdx.x;
    const int lane = tid & 31;
    const int wid = tid >> 5;
    const int gi0 = blockIdx.x * IPB;

    int*   s_item = (int*)(sm + META);           // [64]
    int*   s_len  = (int*)(sm + META + 256);     // [64]
    int*   s_tag  = (int*)(sm + META + 512);     // [512]
    float* b1s    = (float*)(sm + META + 2560);  // [256]
    float* b2s    = (float*)(sm + META + 3584);  // [64]

    // ---- metadata ----
    if (tid < IPB) {
        s_item[tid] = item_ids[gi0 + tid];
        s_len[tid]  = tag_lens[gi0 + tid];
    }
    for (int t = tid; t < IPB * 8; t += NTHREADS) s_tag[t] = tag_ids[gi0 * 8 + t];
    b1s[tid] = b1[tid];
    if (tid < 64) b2s[tid] = b2[tid];
    __syncthreads();

    // ---- gather X (8 unconditional tag loads -> MLP) ----
    for (int s = tid; s < IPB * 16; s += NTHREADS) {
        const int d4 = s & 15;
        const int i  = s >> 4;
        const int id = s_item[i];
        const float4 ei = __ldg((const float4*)(item_table + (size_t)id * 64) + d4);
        const int len = s_len[i];
        float4 tv[8];
        #pragma unroll
        for (int j = 0; j < 8; j++)
            tv[j] = __ldg((const float4*)(tag_table + (size_t)s_tag[i * 8 + j] * 64) + d4);
        float4 sum = make_float4(0.f, 0.f, 0.f, 0.f);
        #pragma unroll
        for (int j = 0; j < 8; j++) {
            const float w = (j < len) ? 1.0f : 0.0f;
            sum.x = fmaf(w, tv[j].x, sum.x);
            sum.y = fmaf(w, tv[j].y, sum.y);
            sum.z = fmaf(w, tv[j].z, sum.z);
            sum.w = fmaf(w, tv[j].w, sum.w);
        }
        const float inv = 1.0f / (float)len;
        const uint32_t o0 = xoff(i, 4 * d4);
        st_hilo4h(sm, XHO + o0, XLO + o0, ei.x, ei.y, ei.z, ei.w);
        const uint32_t o1 = xoff(i, 64 + 4 * d4);
        st_hilo4h(sm, XHO + o1, XLO + o1, sum.x * inv, sum.y * inv, sum.z * inv, sum.w * inv);
    }
    // ---- W1 rows 0..127 -> fp16 single (coalesced) ----
    for (int s = tid; s < 8192; s += NTHREADS) {
        const int k = s >> 6, n4 = s & 63;
        const float4 v = __ldg((const float4*)(W1 + (size_t)k * 256) + n4);
        st_h4(sm, W1O + woff(k, 4 * n4), v);
    }
    // ---- e_dat -> out tail ----
    {
        float* out_dat = out + (size_t)NI * 64;
        for (int s = tid; s < IPB * 16; s += NTHREADS) {
            const int d4 = s & 15, i = s >> 4;
            const float4 v = __ldg((const float4*)(dat_table + (size_t)s_item[i] * 64) + d4);
            ((float4*)(out_dat + (size_t)(gi0 + i) * 64))[d4] = v;
        }
    }
    __syncthreads();

    // ---- GEMM1: C[64,256] = X @ W1 (Ah*B + Al*B) ----
    const int wm = wid >> 2, wn = wid & 3;        // 2x4 warp grid
    const int m0 = wm * 32, n0g = wn * 64;
    float acc[2][8][4];
    #pragma unroll
    for (int a = 0; a < 2; a++)
        #pragma unroll
        for (int j = 0; j < 8; j++)
            #pragma unroll
            for (int q = 0; q < 4; q++) acc[a][j][q] = 0.f;

    #pragma unroll
    for (int k0 = 0; k0 < 128; k0 += 16) {
        uint32_t Ah[2][4], Al[2][4];
        #pragma unroll
        for (int mt = 0; mt < 2; mt++) {
            const int r = m0 + mt * 16 + (lane & 15);
            const uint32_t o = xoff(r, k0 + ((lane >> 4) << 3));
            ldm_x4(Ah[mt], smb + XHO + o);
            ldm_x4(Al[mt], smb + XLO + o);
        }
        uint32_t B[8][2];
        #pragma unroll
        for (int np = 0; np < 4; np++) {
            const int grp = lane >> 3;
            const int kr = k0 + (lane & 7) + ((grp & 1) << 3);
            const int nc = n0g + np * 16 + ((grp >> 1) << 3);
            uint32_t t[4];
            ldm_x4_t(t, smb + W1O + woff(kr, nc));
            B[np * 2][0] = t[0]; B[np * 2][1] = t[1];
            B[np * 2 + 1][0] = t[2]; B[np * 2 + 1][1] = t[3];
        }
        #pragma unroll
        for (int mt = 0; mt < 2; mt++)
            #pragma unroll
            for (int nt = 0; nt < 8; nt++) {
                mma16816h(acc[mt][nt], Ah[mt], B[nt]);
                mma16816h(acc[mt][nt], Al[mt], B[nt]);
            }
    }
    __syncthreads();

    // ---- H = relu(C + b1) -> hi/lo fp16 (over X region); stage W2 ----
    #pragma unroll
    for (int mt = 0; mt < 2; mt++)
        #pragma unroll
        for (int nt = 0; nt < 8; nt++) {
            const int ncol = n0g + nt * 8 + 2 * (lane & 3);
            const float2 bias = *(const float2*)(b1s + ncol);
            const float* c = acc[mt][nt];
            const int r = m0 + mt * 16 + (lane >> 2);
            const uint32_t o0 = hoff(r, ncol);
            st_hilo2h(sm, HHO + o0, HLO + o0,
                      fmaxf(c[0] + bias.x, 0.f), fmaxf(c[1] + bias.y, 0.f));
            const uint32_t o1 = hoff(r + 8, ncol);
            st_hilo2h(sm, HHO + o1, HLO + o1,
                      fmaxf(c[2] + bias.x, 0.f), fmaxf(c[3] + bias.y, 0.f));
        }
    for (int s = tid; s < 4096; s += NTHREADS) {
        const int k = s >> 4, n4 = s & 15;
        const float4 v = __ldg((const float4*)(W2 + (size_t)k * 64) + n4);
        st_h4(sm, W2O + voff(k, 4 * n4), v);
    }
    __syncthreads();

    // ---- GEMM2: O[64,64] = H @ W2 (Ah*B + Al*B) ----
    const int m0b = (wid >> 1) * 16;              // 4x2 warp grid
    const int n0b = (wid & 1) * 32;
    float acc2[4][4];
    #pragma unroll
    for (int j = 0; j < 4; j++)
        #pragma unroll
        for (int q = 0; q < 4; q++) acc2[j][q] = 0.f;

    #pragma unroll
    for (int k0 = 0; k0 < 256; k0 += 16) {
        uint32_t Ah[4], Al[4];
        {
            const int r = m0b + (lane & 15);
            const uint32_t o = hoff(r, k0 + ((lane >> 4) << 3));
            ldm_x4(Ah, smb + HHO + o);
            ldm_x4(Al, smb + HLO + o);
        }
        uint32_t B[4][2];
        #pragma unroll
        for (int np = 0; np < 2; np++) {
            const int grp = lane >> 3;
            const int kr = k0 + (lane & 7) + ((grp & 1) << 3);
            const int nc = n0b + np * 16 + ((grp >> 1) << 3);
            uint32_t t[4];
            ldm_x4_t(t, smb + W2O + voff(kr, nc));
            B[np * 2][0] = t[0]; B[np * 2][1] = t[1];
            B[np * 2 + 1][0] = t[2]; B[np * 2 + 1][1] = t[3];
        }
        #pragma unroll
        for (int nt = 0; nt < 4; nt++) {
            mma16816h(acc2[nt], Ah, B[nt]);
            mma16816h(acc2[nt], Al, B[nt]);
        }
    }

    // ---- epilogue: out = O + b2 ----
    #pragma unroll
    for (int nt = 0; nt < 4; nt++) {
        const int n = n0b + nt * 8 + 2 * (lane & 3);
        const float2 bias = *(const float2*)(b2s + n);
        const int r = gi0 + m0b + (lane >> 2);
        *(float2*)(out + (size_t)r * 64 + n) =
            make_float2(acc2[nt][0] + bias.x, acc2[nt][1] + bias.y);
        *(float2*)(out + (size_t)(r + 8) * 64 + n) =
            make_float2(acc2[nt][2] + bias.x, acc2[nt][3] + bias.y);
    }
}

extern "C" void kernel_launch(void* const* d_in, const int* in_sizes, int n_in,
                              void* d_out, int out_size) {
    cudaFuncSetAttribute(fused_tower_mma2,
                         cudaFuncAttributeMaxDynamicSharedMemorySize, SMEM_BYTES);
    fused_tower_mma2<<<NBLK, NTHREADS, SMEM_BYTES>>>(
        (const int*)d_in[0], (const int*)d_in[1], (const int*)d_in[2],
        (const float*)d_in[3], (const float*)d_in[4], (const float*)d_in[5],
        (const float*)d_in[6], (const float*)d_in[7],
        (const float*)d_in[8], (const float*)d_in[9],
        (float*)d_out);
}

// round 5
// speedup vs baseline: 2.9628x; 1.2280x over previous
#include <cuda_runtime.h>
#include <cuda_fp16.h>
#include <cstdint>

#define NI 16384
#define IPB 64
#define NTHREADS 256
#define NBLK (NI / IPB)

// ---- smem byte regions ----
// phase1: X[64m][128k]f16 16KB @0, W1[128k][256n]f16 64KB @16384
// phase3 (reuse): H[64m][256k]f16 32KB @0, W2[256k][64n]f16 32KB @49152
#define XHO  0u
#define W1O  16384u
#define HHO  0u
#define W2O  49152u
#define META 81920u
#define SMEM_BYTES 86016

static __device__ __forceinline__ uint32_t smem_u32(const void* p) {
    uint32_t a;
    asm("{ .reg .u64 t; cvta.to.shared.u64 t, %1; cvt.u32.u64 %0, t; }" : "=r"(a) : "l"(p));
    return a;
}
// swizzled byte offsets (conflict-free ldmatrix)
static __device__ __forceinline__ uint32_t xoff(int m, int k) {   // 256B rows
    return (uint32_t)(m * 256 + ((k * 2) ^ ((m & 7) * 16)));
}
static __device__ __forceinline__ uint32_t woff(int k, int n) {   // 512B rows
    return (uint32_t)(k * 512 + ((n * 2) ^ ((k & 7) * 16)));
}
static __device__ __forceinline__ uint32_t hoff(int m, int k) {   // 512B rows
    return (uint32_t)(m * 512 + ((k * 2) ^ ((m & 7) * 16)));
}
static __device__ __forceinline__ uint32_t voff(int k, int n) {   // 128B rows
    return (uint32_t)(k * 128 + ((n * 2) ^ ((k & 7) * 16)));
}
static __device__ __forceinline__ uint32_t h2u(__half2 v) {
    return *reinterpret_cast<uint32_t*>(&v);
}
static __device__ __forceinline__ void st_h2(char* sm, uint32_t o, float a, float b) {
    *(uint32_t*)(sm + o) = h2u(__floats2half2_rn(a, b));
}
static __device__ __forceinline__ void st_h4(char* sm, uint32_t o, float4 v) {
    *(uint2*)(sm + o) = make_uint2(h2u(__floats2half2_rn(v.x, v.y)),
                                   h2u(__floats2half2_rn(v.z, v.w)));
}
static __device__ __forceinline__ void ldm_x4(uint32_t* r, uint32_t a) {
    asm volatile("ldmatrix.sync.aligned.m8n8.x4.shared.b16 {%0,%1,%2,%3}, [%4];"
        : "=r"(r[0]), "=r"(r[1]), "=r"(r[2]), "=r"(r[3]) : "r"(a));
}
static __device__ __forceinline__ void ldm_x4_t(uint32_t* r, uint32_t a) {
    asm volatile("ldmatrix.sync.aligned.m8n8.x4.trans.shared.b16 {%0,%1,%2,%3}, [%4];"
        : "=r"(r[0]), "=r"(r[1]), "=r"(r[2]), "=r"(r[3]) : "r"(a));
}
static __device__ __forceinline__ void mma16816h(float* c, const uint32_t* a, const uint32_t* b) {
    asm volatile("mma.sync.aligned.m16n8k16.row.col.f32.f16.f16.f32 "
        "{%0,%1,%2,%3}, {%4,%5,%6,%7}, {%8,%9}, {%0,%1,%2,%3};"
        : "+f"(c[0]), "+f"(c[1]), "+f"(c[2]), "+f"(c[3])
        : "r"(a[0]), "r"(a[1]), "r"(a[2]), "r"(a[3]), "r"(b[0]), "r"(b[1]));
}

__global__ __launch_bounds__(NTHREADS, 2)
void fused_tower_mma3(const int* __restrict__ item_ids,
                      const int* __restrict__ tag_ids,
                      const int* __restrict__ tag_lens,
                      const float* __restrict__ item_table,
                      const float* __restrict__ dat_table,
                      const float* __restrict__ tag_table,
                      const float* __restrict__ W1,
                      const float* __restrict__ b1,
                      const float* __restrict__ W2,
                      const float* __restrict__ b2,
                      float* __restrict__ out)
{
    extern __shared__ __align__(128) char sm[];
    const uint32_t smb = smem_u32(sm);
    const int tid = threadIdx.x;
    const int lane = tid & 31;
    const int wid = tid >> 5;
    const int gi0 = blockIdx.x * IPB;

    int*   s_item = (int*)(sm + META);           // [64]
    int*   s_len  = (int*)(sm + META + 256);     // [64]
    int*   s_tag  = (int*)(sm + META + 512);     // [512]
    float* b1s    = (float*)(sm + META + 2560);  // [256]
    float* b2s    = (float*)(sm + META + 3584);  // [64]

    // ---- metadata ----
    if (tid < IPB) {
        s_item[tid] = item_ids[gi0 + tid];
        s_len[tid]  = tag_lens[gi0 + tid];
    }
    for (int t = tid; t < IPB * 8; t += NTHREADS) s_tag[t] = tag_ids[gi0 * 8 + t];
    b1s[tid] = b1[tid];
    if (tid < 64) b2s[tid] = b2[tid];
    __syncthreads();

    // ---- gather X (8 unconditional tag loads -> MLP) ----
    for (int s = tid; s < IPB * 16; s += NTHREADS) {
        const int d4 = s & 15;
        const int i  = s >> 4;
        const int id = s_item[i];
        const float4 ei = __ldg((const float4*)(item_table + (size_t)id * 64) + d4);
        const int len = s_len[i];
        float4 tv[8];
        #pragma unroll
        for (int j = 0; j < 8; j++)
            tv[j] = __ldg((const float4*)(tag_table + (size_t)s_tag[i * 8 + j] * 64) + d4);
        float4 sum = make_float4(0.f, 0.f, 0.f, 0.f);
        #pragma unroll
        for (int j = 0; j < 8; j++) {
            const float w = (j < len) ? 1.0f : 0.0f;
            sum.x = fmaf(w, tv[j].x, sum.x);
            sum.y = fmaf(w, tv[j].y, sum.y);
            sum.z = fmaf(w, tv[j].z, sum.z);
            sum.w = fmaf(w, tv[j].w, sum.w);
        }
        const float inv = 1.0f / (float)len;
        st_h4(sm, XHO + xoff(i, 4 * d4), ei);
        st_h4(sm, XHO + xoff(i, 64 + 4 * d4),
              make_float4(sum.x * inv, sum.y * inv, sum.z * inv, sum.w * inv));
    }
    // ---- W1 rows 0..127 -> fp16 (coalesced) ----
    for (int s = tid; s < 8192; s += NTHREADS) {
        const int k = s >> 6, n4 = s & 63;
        const float4 v = __ldg((const float4*)(W1 + (size_t)k * 256) + n4);
        st_h4(sm, W1O + woff(k, 4 * n4), v);
    }
    // ---- e_dat -> out tail ----
    {
        float* out_dat = out + (size_t)NI * 64;
        for (int s = tid; s < IPB * 16; s += NTHREADS) {
            const int d4 = s & 15, i = s >> 4;
            const float4 v = __ldg((const float4*)(dat_table + (size_t)s_item[i] * 64) + d4);
            ((float4*)(out_dat + (size_t)(gi0 + i) * 64))[d4] = v;
        }
    }
    __syncthreads();

    // ---- GEMM1: C[64,256] = X @ W1, single fp16 pass ----
    const int wm = wid >> 2, wn = wid & 3;        // 2x4 warp grid
    const int m0 = wm * 32, n0g = wn * 64;
    float acc[2][8][4];
    #pragma unroll
    for (int a = 0; a < 2; a++)
        #pragma unroll
        for (int j = 0; j < 8; j++)
            #pragma unroll
            for (int q = 0; q < 4; q++) acc[a][j][q] = 0.f;

    #pragma unroll
    for (int k0 = 0; k0 < 128; k0 += 16) {
        uint32_t A[2][4];
        #pragma unroll
        for (int mt = 0; mt < 2; mt++) {
            const int r = m0 + mt * 16 + (lane & 15);
            ldm_x4(A[mt], smb + XHO + xoff(r, k0 + ((lane >> 4) << 3)));
        }
        uint32_t B[8][2];
        #pragma unroll
        for (int np = 0; np < 4; np++) {
            const int grp = lane >> 3;
            const int kr = k0 + (lane & 7) + ((grp & 1) << 3);
            const int nc = n0g + np * 16 + ((grp >> 1) << 3);
            uint32_t t[4];
            ldm_x4_t(t, smb + W1O + woff(kr, nc));
            B[np * 2][0] = t[0]; B[np * 2][1] = t[1];
            B[np * 2 + 1][0] = t[2]; B[np * 2 + 1][1] = t[3];
        }
        #pragma unroll
        for (int mt = 0; mt < 2; mt++)
            #pragma unroll
            for (int nt = 0; nt < 8; nt++)
                mma16816h(acc[mt][nt], A[mt], B[nt]);
    }
    __syncthreads();

    // ---- H = relu(C + b1) -> fp16 (over X/W1-low region); stage W2 fp16 ----
    #pragma unroll
    for (int mt = 0; mt < 2; mt++)
        #pragma unroll
        for (int nt = 0; nt < 8; nt++) {
            const int ncol = n0g + nt * 8 + 2 * (lane & 3);
            const float2 bias = *(const float2*)(b1s + ncol);
            const float* c = acc[mt][nt];
            const int r = m0 + mt * 16 + (lane >> 2);
            st_h2(sm, HHO + hoff(r, ncol),
                  fmaxf(c[0] + bias.x, 0.f), fmaxf(c[1] + bias.y, 0.f));
            st_h2(sm, HHO + hoff(r + 8, ncol),
                  fmaxf(c[2] + bias.x, 0.f), fmaxf(c[3] + bias.y, 0.f));
        }
    for (int s = tid; s < 4096; s += NTHREADS) {
        const int k = s >> 4, n4 = s & 15;
        const float4 v = __ldg((const float4*)(W2 + (size_t)k * 64) + n4);
        st_h4(sm, W2O + voff(k, 4 * n4), v);
    }
    __syncthreads();

    // ---- GEMM2: O[64,64] = H @ W2, single fp16 pass ----
    const int m0b = (wid >> 1) * 16;              // 4x2 warp grid
    const int n0b = (wid & 1) * 32;
    float acc2[4][4];
    #pragma unroll
    for (int j = 0; j < 4; j++)
        #pragma unroll
        for (int q = 0; q < 4; q++) acc2[j][q] = 0.f;

    #pragma unroll
    for (int k0 = 0; k0 < 256; k0 += 16) {
        uint32_t A[4];
        {
            const int r = m0b + (lane & 15);
            ldm_x4(A, smb + HHO + hoff(r, k0 + ((lane >> 4) << 3)));
        }
        uint32_t B[4][2];
        #pragma unroll
        for (int np = 0; np < 2; np++) {
            const int grp = lane >> 3;
            const int kr = k0 + (lane & 7) + ((grp & 1) << 3);
            const int nc = n0b + np * 16 + ((grp >> 1) << 3);
            uint32_t t[4];
            ldm_x4_t(t, smb + W2O + voff(kr, nc));
            B[np * 2][0] = t[0]; B[np * 2][1] = t[1];
            B[np * 2 + 1][0] = t[2]; B[np * 2 + 1][1] = t[3];
        }
        #pragma unroll
        for (int nt = 0; nt < 4; nt++)
            mma16816h(acc2[nt], A, B[nt]);
    }

    // ---- epilogue: out = O + b2 ----
    #pragma unroll
    for (int nt = 0; nt < 4; nt++) {
        const int n = n0b + nt * 8 + 2 * (lane & 3);
        const float2 bias = *(const float2*)(b2s + n);
        const int r = gi0 + m0b + (lane >> 2);
        *(float2*)(out + (size_t)r * 64 + n) =
            make_float2(acc2[nt][0] + bias.x, acc2[nt][1] + bias.y);
        *(float2*)(out + (size_t)(r + 8) * 64 + n) =
            make_float2(acc2[nt][2] + bias.x, acc2[nt][3] + bias.y);
    }
}

extern "C" void kernel_launch(void* const* d_in, const int* in_sizes, int n_in,
                              void* d_out, int out_size) {
    cudaFuncSetAttribute(fused_tower_mma3,
                         cudaFuncAttributeMaxDynamicSharedMemorySize, SMEM_BYTES);
    fused_tower_mma3<<<NBLK, NTHREADS, SMEM_BYTES>>>(
        (const int*)d_in[0], (const int*)d_in[1], (const int*)d_in[2],
        (const float*)d_in[3], (const float*)d_in[4], (const float*)d_in[5],
        (const float*)d_in[6], (const float*)d_in[7],
        (const float*)d_in[8], (const float*)d_in[9],
        (float*)d_out);
}

// round 6
// speedup vs baseline: 3.3283x; 1.1233x over previous
#include <cuda_runtime.h>
#include <cuda_fp16.h>
#include <cstdint>

#define NI 16384
#define IPB 64
#define NTHREADS 256
#define NBLK (NI / IPB)

// ---- smem byte regions ----
// phase1: X[64m][128k]f16 16KB @0, W1 image 64KB @16384
// phase3 (reuse): H[64m][256k]f16 32KB @0, W2 image 32KB @32768 (dead W1 area)
#define XHO  0u
#define W1O  16384u
#define HHO  0u
#define W2O  32768u
#define META 81920u
#define SMEM_BYTES 86016

__device__ __align__(16) unsigned char g_w1h[65536];   // pre-swizzled fp16 W1 image
__device__ __align__(16) unsigned char g_w2h[32768];   // pre-swizzled fp16 W2 image

static __device__ __forceinline__ uint32_t smem_u32(const void* p) {
    uint32_t a;
    asm("{ .reg .u64 t; cvta.to.shared.u64 t, %1; cvt.u32.u64 %0, t; }" : "=r"(a) : "l"(p));
    return a;
}
static __device__ __forceinline__ uint64_t gmem_u64(const void* p) {
    uint64_t a;
    asm("cvta.to.global.u64 %0, %1;" : "=l"(a) : "l"(p));
    return a;
}
// swizzled byte offsets (conflict-free ldmatrix)
static __device__ __forceinline__ uint32_t xoff(int m, int k) {   // 256B rows
    return (uint32_t)(m * 256 + ((k * 2) ^ ((m & 7) * 16)));
}
static __device__ __forceinline__ uint32_t woff(int k, int n) {   // 512B rows
    return (uint32_t)(k * 512 + ((n * 2) ^ ((k & 7) * 16)));
}
static __device__ __forceinline__ uint32_t hoff(int m, int k) {   // 512B rows
    return (uint32_t)(m * 512 + ((k * 2) ^ ((m & 7) * 16)));
}
static __device__ __forceinline__ uint32_t voff(int k, int n) {   // 128B rows
    return (uint32_t)(k * 128 + ((n * 2) ^ ((k & 7) * 16)));
}
static __device__ __forceinline__ uint32_t h2u(__half2 v) {
    return *reinterpret_cast<uint32_t*>(&v);
}
static __device__ __forceinline__ void st_h2(char* sm, uint32_t o, float a, float b) {
    *(uint32_t*)(sm + o) = h2u(__floats2half2_rn(a, b));
}
static __device__ __forceinline__ void st_h4(char* sm, uint32_t o, float4 v) {
    *(uint2*)(sm + o) = make_uint2(h2u(__floats2half2_rn(v.x, v.y)),
                                   h2u(__floats2half2_rn(v.z, v.w)));
}
static __device__ __forceinline__ void cp16(uint32_t dst, uint64_t src) {
    asm volatile("cp.async.cg.shared.global [%0], [%1], 16;" :: "r"(dst), "l"(src) : "memory");
}
#define CP_COMMIT() asm volatile("cp.async.commit_group;" ::: "memory")
#define CP_WAIT0()  asm volatile("cp.async.wait_group 0;" ::: "memory")

static __device__ __forceinline__ void ldm_x4(uint32_t* r, uint32_t a) {
    asm volatile("ldmatrix.sync.aligned.m8n8.x4.shared.b16 {%0,%1,%2,%3}, [%4];"
        : "=r"(r[0]), "=r"(r[1]), "=r"(r[2]), "=r"(r[3]) : "r"(a));
}
static __device__ __forceinline__ void ldm_x4_t(uint32_t* r, uint32_t a) {
    asm volatile("ldmatrix.sync.aligned.m8n8.x4.trans.shared.b16 {%0,%1,%2,%3}, [%4];"
        : "=r"(r[0]), "=r"(r[1]), "=r"(r[2]), "=r"(r[3]) : "r"(a));
}
static __device__ __forceinline__ void mma16816h(float* c, const uint32_t* a, const uint32_t* b) {
    asm volatile("mma.sync.aligned.m16n8k16.row.col.f32.f16.f16.f32 "
        "{%0,%1,%2,%3}, {%4,%5,%6,%7}, {%8,%9}, {%0,%1,%2,%3};"
        : "+f"(c[0]), "+f"(c[1]), "+f"(c[2]), "+f"(c[3])
        : "r"(a[0]), "r"(a[1]), "r"(a[2]), "r"(a[3]), "r"(b[0]), "r"(b[1]));
}

// ---- prologue: W1/W2 fp32 -> pre-swizzled fp16 smem images ----
__global__ __launch_bounds__(256)
void convert_weights(const float* __restrict__ W1, const float* __restrict__ W2) {
    const int t = blockIdx.x * blockDim.x + threadIdx.x;   // 0..16383
    {
        const int k = t >> 7, n2 = t & 127;                // W1 row k (0..127), n = 2*n2
        const float2 v = *(const float2*)(W1 + (size_t)k * 256 + 2 * n2);
        *(uint32_t*)(g_w1h + woff(k, 2 * n2)) = h2u(__floats2half2_rn(v.x, v.y));
    }
    if (t < 8192) {
        const int k = t >> 5, n2 = t & 31;                 // W2 row k (0..255)
        const float2 v = *(const float2*)(W2 + (size_t)k * 64 + 2 * n2);
        *(uint32_t*)(g_w2h + voff(k, 2 * n2)) = h2u(__floats2half2_rn(v.x, v.y));
    }
}

__global__ __launch_bounds__(NTHREADS, 2)
void fused_tower_mma4(const int* __restrict__ item_ids,
                      const int* __restrict__ tag_ids,
                      const int* __restrict__ tag_lens,
                      const float* __restrict__ item_table,
                      const float* __restrict__ dat_table,
                      const float* __restrict__ tag_table,
                      const float* __restrict__ b1,
                      const float* __restrict__ b2,
                      float* __restrict__ out)
{
    extern __shared__ __align__(128) char sm[];
    const uint32_t smb = smem_u32(sm);
    const int tid = threadIdx.x;
    const int lane = tid & 31;
    const int wid = tid >> 5;
    const int gi0 = blockIdx.x * IPB;

    int*   s_item = (int*)(sm + META);           // [64]
    int*   s_len  = (int*)(sm + META + 256);     // [64]
    int*   s_tag  = (int*)(sm + META + 512);     // [512]
    float* b1s    = (float*)(sm + META + 2560);  // [256]
    float* b2s    = (float*)(sm + META + 3584);  // [64]

    // ---- kick off W1 image DMA first (overlaps the whole gather phase) ----
    {
        const uint64_t src = gmem_u64(g_w1h);
        #pragma unroll
        for (int j = 0; j < 16; j++) {
            const uint32_t c = (uint32_t)tid + j * 256;    // 4096 chunks x 16B
            cp16(smb + W1O + c * 16, src + c * 16);
        }
        CP_COMMIT();
    }

    // ---- metadata ----
    if (tid < IPB) {
        s_item[tid] = item_ids[gi0 + tid];
        s_len[tid]  = tag_lens[gi0 + tid];
    }
    for (int t = tid; t < IPB * 8; t += NTHREADS) s_tag[t] = tag_ids[gi0 * 8 + t];
    b1s[tid] = b1[tid];
    if (tid < 64) b2s[tid] = b2[tid];
    __syncthreads();

    // ---- gather X (8 unconditional tag loads -> MLP) ----
    for (int s = tid; s < IPB * 16; s += NTHREADS) {
        const int d4 = s & 15;
        const int i  = s >> 4;
        const int id = s_item[i];
        const float4 ei = __ldg((const float4*)(item_table + (size_t)id * 64) + d4);
        const int len = s_len[i];
        float4 tv[8];
        #pragma unroll
        for (int j = 0; j < 8; j++)
            tv[j] = __ldg((const float4*)(tag_table + (size_t)s_tag[i * 8 + j] * 64) + d4);
        float4 sum = make_float4(0.f, 0.f, 0.f, 0.f);
        #pragma unroll
        for (int j = 0; j < 8; j++) {
            const float w = (j < len) ? 1.0f : 0.0f;
            sum.x = fmaf(w, tv[j].x, sum.x);
            sum.y = fmaf(w, tv[j].y, sum.y);
            sum.z = fmaf(w, tv[j].z, sum.z);
            sum.w = fmaf(w, tv[j].w, sum.w);
        }
        const float inv = 1.0f / (float)len;
        st_h4(sm, XHO + xoff(i, 4 * d4), ei);
        st_h4(sm, XHO + xoff(i, 64 + 4 * d4),
              make_float4(sum.x * inv, sum.y * inv, sum.z * inv, sum.w * inv));
    }
    // ---- e_dat -> out tail ----
    {
        float* out_dat = out + (size_t)NI * 64;
        for (int s = tid; s < IPB * 16; s += NTHREADS) {
            const int d4 = s & 15, i = s >> 4;
            const float4 v = __ldg((const float4*)(dat_table + (size_t)s_item[i] * 64) + d4);
            ((float4*)(out_dat + (size_t)(gi0 + i) * 64))[d4] = v;
        }
    }
    CP_WAIT0();
    __syncthreads();

    // ---- GEMM1: C[64,256] = X @ W1, single fp16 pass ----
    const int wm = wid >> 2, wn = wid & 3;        // 2x4 warp grid
    const int m0 = wm * 32, n0g = wn * 64;
    float acc[2][8][4];
    #pragma unroll
    for (int a = 0; a < 2; a++)
        #pragma unroll
        for (int j = 0; j < 8; j++)
            #pragma unroll
            for (int q = 0; q < 4; q++) acc[a][j][q] = 0.f;

    #pragma unroll
    for (int k0 = 0; k0 < 128; k0 += 16) {
        uint32_t A[2][4];
        #pragma unroll
        for (int mt = 0; mt < 2; mt++) {
            const int r = m0 + mt * 16 + (lane & 15);
            ldm_x4(A[mt], smb + XHO + xoff(r, k0 + ((lane >> 4) << 3)));
        }
        uint32_t B[8][2];
        #pragma unroll
        for (int np = 0; np < 4; np++) {
            const int grp = lane >> 3;
            const int kr = k0 + (lane & 7) + ((grp & 1) << 3);
            const int nc = n0g + np * 16 + ((grp >> 1) << 3);
            uint32_t t[4];
            ldm_x4_t(t, smb + W1O + woff(kr, nc));
            B[np * 2][0] = t[0]; B[np * 2][1] = t[1];
            B[np * 2 + 1][0] = t[2]; B[np * 2 + 1][1] = t[3];
        }
        #pragma unroll
        for (int mt = 0; mt < 2; mt++)
            #pragma unroll
            for (int nt = 0; nt < 8; nt++)
                mma16816h(acc[mt][nt], A[mt], B[nt]);
    }
    __syncthreads();

    // ---- W2 image DMA (into dead W1 area) + H = relu(C + b1) -> fp16 ----
    {
        const uint64_t src = gmem_u64(g_w2h);
        #pragma unroll
        for (int j = 0; j < 8; j++) {
            const uint32_t c = (uint32_t)tid + j * 256;    // 2048 chunks x 16B
            cp16(smb + W2O + c * 16, src + c * 16);
        }
        CP_COMMIT();
    }
    #pragma unroll
    for (int mt = 0; mt < 2; mt++)
        #pragma unroll
        for (int nt = 0; nt < 8; nt++) {
            const int ncol = n0g + nt * 8 + 2 * (lane & 3);
            const float2 bias = *(const float2*)(b1s + ncol);
            const float* c = acc[mt][nt];
            const int r = m0 + mt * 16 + (lane >> 2);
            st_h2(sm, HHO + hoff(r, ncol),
                  fmaxf(c[0] + bias.x, 0.f), fmaxf(c[1] + bias.y, 0.f));
            st_h2(sm, HHO + hoff(r + 8, ncol),
                  fmaxf(c[2] + bias.x, 0.f), fmaxf(c[3] + bias.y, 0.f));
        }
    CP_WAIT0();
    __syncthreads();

    // ---- GEMM2: O[64,64] = H @ W2, single fp16 pass ----
    const int m0b = (wid >> 1) * 16;              // 4x2 warp grid
    const int n0b = (wid & 1) * 32;
    float acc2[4][4];
    #pragma unroll
    for (int j = 0; j < 4; j++)
        #pragma unroll
        for (int q = 0; q < 4; q++) acc2[j][q] = 0.f;

    #pragma unroll
    for (int k0 = 0; k0 < 256; k0 += 16) {
        uint32_t A[4];
        {
            const int r = m0b + (lane & 15);
            ldm_x4(A, smb + HHO + hoff(r, k0 + ((lane >> 4) << 3)));
        }
        uint32_t B[4][2];
        #pragma unroll
        for (int np = 0; np < 2; np++) {
            const int grp = lane >> 3;
            const int kr = k0 + (lane & 7) + ((grp & 1) << 3);
            const int nc = n0b + np * 16 + ((grp >> 1) << 3);
            uint32_t t[4];
            ldm_x4_t(t, smb + W2O + voff(kr, nc));
            B[np * 2][0] = t[0]; B[np * 2][1] = t[1];
            B[np * 2 + 1][0] = t[2]; B[np * 2 + 1][1] = t[3];
        }
        #pragma unroll
        for (int nt = 0; nt < 4; nt++)
            mma16816h(acc2[nt], A, B[nt]);
    }

    // ---- epilogue: out = O + b2 ----
    #pragma unroll
    for (int nt = 0; nt < 4; nt++) {
        const int n = n0b + nt * 8 + 2 * (lane & 3);
        const float2 bias = *(const float2*)(b2s + n);
        const int r = gi0 + m0b + (lane >> 2);
        *(float2*)(out + (size_t)r * 64 + n) =
            make_float2(acc2[nt][0] + bias.x, acc2[nt][1] + bias.y);
        *(float2*)(out + (size_t)(r + 8) * 64 + n) =
            make_float2(acc2[nt][2] + bias.x, acc2[nt][3] + bias.y);
    }
}

extern "C" void kernel_launch(void* const* d_in, const int* in_sizes, int n_in,
                              void* d_out, int out_size) {
    cudaFuncSetAttribute(fused_tower_mma4,
                         cudaFuncAttributeMaxDynamicSharedMemorySize, SMEM_BYTES);
    convert_weights<<<64, 256>>>((const float*)d_in[6], (const float*)d_in[8]);
    fused_tower_mma4<<<NBLK, NTHREADS, SMEM_BYTES>>>(
        (const int*)d_in[0], (const int*)d_in[1], (const int*)d_in[2],
        (const float*)d_in[3], (const float*)d_in[4], (const float*)d_in[5],
        (const float*)d_in[7], (const float*)d_in[9],
        (float*)d_out);
}